// round 13
// baseline (speedup 1.0000x reference)
#include <cuda_runtime.h>
#include <cuda.h>
#include <cuda_fp16.h>
#include <cstdint>
#include <cstddef>
#include <cstring>

// ----------------------------- problem sizes ------------------------------
#define BB 4096
#define DD 1024
#define HH 4096
#define NSTEPS 64
#define NEV (NSTEPS*4)        // 256 RHS evaluations

// ------------------------------ GEMM tiling -------------------------------
#define BMP 256               // pair M (128 rows per CTA)
#define BNP 256               // pair N (128 B-rows per CTA)
#define BK 64                 // fp16 per K-chunk = 128 B (SW128 atom)
#define STAGES 6
#define TILE_BYTES 16384
#define CHUNK_BYTES (2*TILE_BYTES)
#define PAIR_CHUNK_BYTES (2*CHUNK_BYTES)
#define SMEM_REQ (STAGES*CHUNK_BYTES + 2048)
#define NPAIRS 64
#define GRIDC (2*NPAIRS)
#define MT 16

#define G1_NCH (DD/BK)        // 16
#define G2_NCH (HH/BK)        // 64

// idesc kind::f16 cg2: dtype=F32(1<<4), a/btype=F16, N=256, M=256
#define IDESC_CG2 ((1u<<4) | (32u<<17) | (16u<<24))

#if defined(__CUDA_ARCH__) && (defined(__CUDA_ARCH_FEAT_SM103_ALL) || defined(__CUDA_ARCH_FEAT_SM100_ALL) || defined(__CUDA_ARCH_FEAT_SM101_ALL))
#define HAS_TCGEN05 1
#else
#define HAS_TCGEN05 0
#endif

// --------------------------- persistent scratch ---------------------------
__device__ __align__(1024) __half g_W1h[(size_t)HH * DD];
__device__ __align__(1024) __half g_W2h[(size_t)DD * HH];
__device__ __align__(1024) __half g_xe [(size_t)BB * DD];
__device__ __align__(1024) __half g_h  [(size_t)BB * HH];
__device__ __align__(1024) float  g_acc[(size_t)BB * DD];
// dependency flags: flagA[ev][mi] (xe ready, target 8), flagH[ev][mi] (h ready, target 32)
__device__ unsigned int g_flagA[(NEV + 1) * MT];
__device__ unsigned int g_flagH[NEV * MT];

__device__ __forceinline__ float tanh_fast(float x) {
    float y; asm("tanh.approx.f32 %0, %1;" : "=f"(y) : "f"(x)); return y;
}

// bounded acquire-spin on a dependency flag
__device__ __forceinline__ void flag_wait(unsigned int* f, unsigned int tgt) {
    for (int i = 0; i < 4000000; i++) {
        unsigned int v;
        asm volatile("ld.acquire.gpu.u32 %0, [%1];" : "=r"(v) : "l"(f));
        if (v >= tgt) return;
    }
}

#if HAS_TCGEN05
// ------------------------------ PTX helpers -------------------------------
__device__ __forceinline__ uint32_t smem_u32(const void* p) {
    uint32_t a;
    asm("{ .reg .u64 t; cvta.to.shared.u64 t, %1; cvt.u32.u64 %0, t; }" : "=r"(a) : "l"(p));
    return a;
}
__device__ __forceinline__ uint32_t ctarank() {
    uint32_t r; asm("mov.u32 %0, %%cluster_ctarank;" : "=r"(r)); return r;
}
__device__ __forceinline__ void cluster_sync() {
    asm volatile("barrier.cluster.arrive.aligned;" ::: "memory");
    asm volatile("barrier.cluster.wait.aligned;" ::: "memory");
}
__device__ __forceinline__ void mbar_init(uint32_t mbar, uint32_t count) {
    asm volatile("mbarrier.init.shared.b64 [%0], %1;" :: "r"(mbar), "r"(count) : "memory");
}
__device__ __forceinline__ void mbar_expect_tx(uint32_t mbar, uint32_t bytes) {
    asm volatile("mbarrier.arrive.expect_tx.shared.b64 _, [%0], %1;" :: "r"(mbar), "r"(bytes) : "memory");
}
__device__ __forceinline__ void mbar_wait(uint32_t mbar, uint32_t parity) {
    for (int i = 0; i < 4000000; i++) {
        uint32_t done;
        asm volatile(
            "{\n\t.reg .pred P;\n\t"
            "mbarrier.try_wait.parity.acquire.cta.shared::cta.b64 P, [%1], %2;\n\t"
            "selp.b32 %0, 1, 0, P;\n\t}"
            : "=r"(done) : "r"(mbar), "r"(parity) : "memory");
        if (done) return;
    }
}
__device__ __forceinline__ void mbar_arrive_leader(uint32_t mbar) {
    uint32_t la = mbar & 0xFEFFFFFFu;
    asm volatile("mbarrier.arrive.shared::cluster.b64 _, [%0];" :: "r"(la) : "memory");
}
__device__ __forceinline__ void tma_load_2d_cg2(uint32_t smem_dst, const CUtensorMap* map,
                                                int32_t cx, int32_t cy, uint32_t mbar) {
    uint32_t lb = mbar & 0xFEFFFFFFu;
    asm volatile(
        "cp.async.bulk.tensor.2d.cta_group::2.shared::cluster.global.tile.mbarrier::complete_tx::bytes "
        "[%0], [%1, {%2, %3}], [%4];"
        :: "r"(smem_dst), "l"(map), "r"(cx), "r"(cy), "r"(lb) : "memory");
}
__device__ __forceinline__ uint64_t make_desc(uint32_t addr) {
    const uint64_t base = (uint64_t(2) << 61) | (uint64_t(1) << 46) |
                          (uint64_t(64) << 32) | (uint64_t(1) << 16);
    return base | ((uint64_t)(addr >> 4) & 0x3FFF);
}
__device__ __forceinline__ void mma_f16_ss_cg2(uint32_t d_tmem, uint64_t a_desc, uint64_t b_desc,
                                               uint32_t idesc, uint32_t enable) {
    asm volatile(
        "{\n\t.reg .pred p;\n\t"
        "setp.ne.u32 p, %5, 0;\n\t"
        "tcgen05.mma.cta_group::2.kind::f16 [%0], %1, %2, %3, "
        "{%4, %4, %4, %4, %4, %4, %4, %4}, p;\n\t}"
        :: "r"(d_tmem), "l"(a_desc), "l"(b_desc), "r"(idesc), "r"(0u), "r"(enable) : "memory");
}
__device__ __forceinline__ void tc_commit_mc2(uint32_t mbar) {
    asm volatile(
        "tcgen05.commit.cta_group::2.mbarrier::arrive::one.shared::cluster.multicast::cluster.b64 [%0], %1;"
        :: "r"(mbar), "h"((uint16_t)0x3) : "memory");
}

#define TC_ALLOC_CG2(slot, n)  asm volatile("tcgen05.alloc.cta_group::2.sync.aligned.shared::cta.b32 [%0], %1;" :: "r"(slot), "r"((uint32_t)(n)) : "memory")
#define TC_RELINQ_CG2()        asm volatile("tcgen05.relinquish_alloc_permit.cta_group::2.sync.aligned;")
#define TC_DEALLOC_CG2(t, n)   asm volatile("tcgen05.dealloc.cta_group::2.sync.aligned.b32 %0, %1;" :: "r"(t), "r"((uint32_t)(n)))
#define TC_WAIT_LD()       asm volatile("tcgen05.wait::ld.sync.aligned;" ::: "memory")
#define TC_FENCE_AFTER()   asm volatile("tcgen05.fence::after_thread_sync;" ::: "memory")
#define TC_FENCE_BEFORE()  asm volatile("tcgen05.fence::before_thread_sync;" ::: "memory")

#define LDTM_X32(r, addr) \
    asm volatile( \
        "tcgen05.ld.sync.aligned.32x32b.x32.b32 " \
        "{%0, %1, %2, %3, %4, %5, %6, %7, " \
        " %8, %9, %10, %11, %12, %13, %14, %15, " \
        " %16, %17, %18, %19, %20, %21, %22, %23, " \
        " %24, %25, %26, %27, %28, %29, %30, %31}, [%32];" \
        : "=r"((r)[0]),  "=r"((r)[1]),  "=r"((r)[2]),  "=r"((r)[3]), \
          "=r"((r)[4]),  "=r"((r)[5]),  "=r"((r)[6]),  "=r"((r)[7]), \
          "=r"((r)[8]),  "=r"((r)[9]),  "=r"((r)[10]), "=r"((r)[11]), \
          "=r"((r)[12]), "=r"((r)[13]), "=r"((r)[14]), "=r"((r)[15]), \
          "=r"((r)[16]), "=r"((r)[17]), "=r"((r)[18]), "=r"((r)[19]), \
          "=r"((r)[20]), "=r"((r)[21]), "=r"((r)[22]), "=r"((r)[23]), \
          "=r"((r)[24]), "=r"((r)[25]), "=r"((r)[26]), "=r"((r)[27]), \
          "=r"((r)[28]), "=r"((r)[29]), "=r"((r)[30]), "=r"((r)[31]) \
        : "r"(addr))
#endif  // HAS_TCGEN05

// ------------------------------- megakernel -------------------------------
// One launch, zero global barriers. Per eval, pair p (mi = p&15, niBase = p>>4)
// processes 4 GEMM1 tiles (ni = niBase+4k mod 16) then 1 GEMM2 tile (mi,niBase).
// Producer warp gates A-loads on dependency flags; everything else flows
// through the existing mbarrier pipeline, so the TMA/MMA pipeline never drains.
__global__ void __launch_bounds__(256, 1) __cluster_dims__(2, 1, 1) ode_mega_kernel(
    const __grid_constant__ CUtensorMap tmA1,
    const __grid_constant__ CUtensorMap tmB1,
    const __grid_constant__ CUtensorMap tmA2,
    const __grid_constant__ CUtensorMap tmB2,
    const float* __restrict__ b1,
    const float* __restrict__ b2,
    float* __restrict__ xc,
    const float* __restrict__ W1raw,
    const float* __restrict__ W2raw)
{
    const float dt = 1.0f / (float)NSTEPS;
    const float s6 = dt / 6.0f;

#if HAS_TCGEN05
    extern __shared__ char smem[];
    uint32_t sbase = smem_u32(smem);
    uint32_t tile0 = (sbase + 1023u) & ~1023u;
    uint32_t ctrl  = tile0 + STAGES * CHUNK_BYTES;
    uint32_t mb_full    = ctrl;
    uint32_t mb_empty   = ctrl + 64;
    uint32_t mb_accfull = ctrl + 128;
    uint32_t mb_accfree = ctrl + 160;
    uint32_t tmem_slot  = ctrl + 192;

    const int tid = threadIdx.x, wid = tid >> 5, lane = tid & 31;
    const uint32_t rank = ctarank();
    const int pairId = (int)(blockIdx.x >> 1);
    const int mi     = pairId & (MT - 1);
    const int niBase = pairId >> 4;          // 0..3

    if (wid == 0) { TC_ALLOC_CG2(tmem_slot, 512); }
    if (tid == 0) {
        for (int s = 0; s < STAGES; s++) {
            mbar_init(mb_full  + 8*s, 1);
            mbar_init(mb_empty + 8*s, 1);
        }
        mbar_init(mb_accfull + 0, 1);  mbar_init(mb_accfull + 8, 1);
        mbar_init(mb_accfree + 0, 2);  mbar_init(mb_accfree + 8, 2);
    }
    __syncthreads();
    cluster_sync();

    uint32_t tmem;
    asm volatile("ld.shared.b32 %0, [%1];" : "=r"(tmem) : "r"(tmem_slot));

    // ---- producer: warp 4 lane 0, BOTH CTAs ----
    if (wid == 4 && lane == 0) {
        int pr_s = 0; uint32_t pr_ph = 1;
        const int mself = mi * BMP + (int)rank * 128;
        for (int ev = 0; ev < NEV; ev++) {
            // GEMM1: A = xe[mi block] -- ready when prev eval's GEMM2 wrote it
            if (ev > 0) {
                flag_wait(&g_flagA[ev * MT + mi], 8);
                asm volatile("fence.proxy.async;" ::: "memory");
            }
            for (int k4 = 0; k4 < 4; k4++) {
                const int ni = (niBase + 4*k4) & (MT - 1);
                const int nself = ni * BNP + (int)rank * 128;
                for (int c = 0; c < G1_NCH; c++) {
                    mbar_wait(mb_empty + 8*pr_s, pr_ph);
                    uint32_t st = tile0 + pr_s * CHUNK_BYTES;
                    if (rank == 0) mbar_expect_tx(mb_full + 8*pr_s, PAIR_CHUNK_BYTES);
                    tma_load_2d_cg2(st,              &tmA1, c*BK, mself, mb_full + 8*pr_s);
                    tma_load_2d_cg2(st + TILE_BYTES, &tmB1, c*BK, nself, mb_full + 8*pr_s);
                    if (++pr_s == STAGES) { pr_s = 0; pr_ph ^= 1; }
                }
            }
            // GEMM2: A = h[mi block] -- ready when all 16 GEMM1 (mi,*) tiles done
            flag_wait(&g_flagH[ev * MT + mi], 32);
            asm volatile("fence.proxy.async;" ::: "memory");
            {
                const int nself = niBase * BNP + (int)rank * 128;
                for (int c = 0; c < G2_NCH; c++) {
                    mbar_wait(mb_empty + 8*pr_s, pr_ph);
                    uint32_t st = tile0 + pr_s * CHUNK_BYTES;
                    if (rank == 0) mbar_expect_tx(mb_full + 8*pr_s, PAIR_CHUNK_BYTES);
                    tma_load_2d_cg2(st,              &tmA2, c*BK, mself, mb_full + 8*pr_s);
                    tma_load_2d_cg2(st + TILE_BYTES, &tmB2, c*BK, nself, mb_full + 8*pr_s);
                    if (++pr_s == STAGES) { pr_s = 0; pr_ph ^= 1; }
                }
            }
        }
    }

    // ---- MMA issuer: warp 5 lane 0, LEADER only ----
    if (rank == 0 && wid == 5 && lane == 0) {
        int mm_s = 0; uint32_t mm_ph = 0;
        int mm_j = 0;
        for (int ev = 0; ev < NEV; ev++) {
            for (int ti = 0; ti < 5; ti++, mm_j++) {
                const int nch = (ti < 4) ? G1_NCH : G2_NCH;
                const uint32_t b = (uint32_t)(mm_j & 1);
                const uint32_t dtm = tmem + b * 256;
                if (mm_j >= 2) { mbar_wait(mb_accfree + 8*b, (uint32_t)(((mm_j - 2) >> 1) & 1)); TC_FENCE_AFTER(); }
                uint32_t en = 0;
                for (int c = 0; c < nch; c++) {
                    mbar_wait(mb_full + 8*mm_s, mm_ph);
                    uint32_t st = tile0 + mm_s * CHUNK_BYTES;
                    uint64_t da = make_desc(st);
                    uint64_t db = make_desc(st + TILE_BYTES);
                    #pragma unroll
                    for (int k = 0; k < 4; k++) { mma_f16_ss_cg2(dtm, da + 2*k, db + 2*k, IDESC_CG2, en); en = 1; }
                    tc_commit_mc2(mb_empty + 8*mm_s);
                    if (++mm_s == STAGES) { mm_s = 0; mm_ph ^= 1; }
                }
                tc_commit_mc2(mb_accfull + 8*b);
            }
        }
    }

    // ---- epilogue: warps 0-3, BOTH CTAs ----
    if (wid < 4) {
        int ep_j = 0;
        const int m = mi * BMP + (int)rank * 128 + wid * 32 + lane;
        for (int ev = 0; ev < NEV; ev++) {
            const int e = ev & 3;
            const float wcoef = (e == 1 || e == 2) ? 2.0f : 1.0f;
            const float ccn   = (e == 0 || e == 1) ? 0.5f*dt : (e == 2 ? dt : 0.0f);
            const int first = (e == 0), last = (e == 3);
            for (int ti = 0; ti < 5; ti++, ep_j++) {
                const uint32_t b = (uint32_t)(ep_j & 1);
                mbar_wait(mb_accfull + 8*b, (uint32_t)((ep_j >> 1) & 1));
                TC_FENCE_AFTER();
                if (ti < 4) {
                    // GEMM1 tile: h = tanh(C + b1), fp16
                    const int ni = (niBase + 4*ti) & (MT - 1);
                    const int n0 = ni * BNP;
                    for (int nb = 0; nb < 8; nb++) {
                        uint32_t rh[32];
                        LDTM_X32(rh, tmem + b * 256 + nb * 32);
                        TC_WAIT_LD();
                        const int nc = n0 + nb * 32;
                        uint32_t packed[16];
                        #pragma unroll
                        for (int q = 0; q < 16; q++) {
                            float v0 = __uint_as_float(rh[2*q])   + b1[nc + 2*q];
                            float v1 = __uint_as_float(rh[2*q+1]) + b1[nc + 2*q+1];
                            __half2 h2 = __floats2half2_rn(tanh_fast(v0), tanh_fast(v1));
                            packed[q] = *reinterpret_cast<uint32_t*>(&h2);
                        }
                        uint4* dst = reinterpret_cast<uint4*>(g_h + (size_t)m * HH + nc);
                        #pragma unroll
                        for (int q = 0; q < 4; q++) dst[q] = reinterpret_cast<uint4*>(packed)[q];
                    }
                } else {
                    // GEMM2 tile: RK4 accumulate / final state update + next xe
                    const int n0 = niBase * BNP;
                    for (int nb = 0; nb < 8; nb++) {
                        uint32_t rh[32];
                        LDTM_X32(rh, tmem + b * 256 + nb * 32);
                        TC_WAIT_LD();
                        const int nc = n0 + nb * 32;
                        float vals[32];
                        #pragma unroll
                        for (int q = 0; q < 32; q++)
                            vals[q] = __uint_as_float(rh[q]) + b2[nc + q];
                        const size_t off = (size_t)m * DD + nc;
                        uint32_t packed[16];
                        if (!last) {
                            float4* da = reinterpret_cast<float4*>(g_acc + off);
                            const float4* dx = reinterpret_cast<const float4*>(xc + off);
                            #pragma unroll
                            for (int q = 0; q < 8; q++) {
                                float4 v = reinterpret_cast<float4*>(vals)[q];
                                float4 a;
                                if (first) { a = v; }
                                else {
                                    a = da[q];
                                    a.x += wcoef * v.x; a.y += wcoef * v.y;
                                    a.z += wcoef * v.z; a.w += wcoef * v.w;
                                }
                                da[q] = a;
                                float4 xo = dx[q];
                                __half2 h0 = __floats2half2_rn(fmaf(ccn, v.x, xo.x), fmaf(ccn, v.y, xo.y));
                                __half2 h1 = __floats2half2_rn(fmaf(ccn, v.z, xo.z), fmaf(ccn, v.w, xo.w));
                                packed[2*q]   = *reinterpret_cast<uint32_t*>(&h0);
                                packed[2*q+1] = *reinterpret_cast<uint32_t*>(&h1);
                            }
                        } else {
                            const float4* da = reinterpret_cast<const float4*>(g_acc + off);
                            float4* dx = reinterpret_cast<float4*>(xc + off);
                            #pragma unroll
                            for (int q = 0; q < 8; q++) {
                                float4 v = reinterpret_cast<float4*>(vals)[q];
                                float4 a = da[q];
                                float4 xo = dx[q];
                                float4 xn;
                                xn.x = fmaf(s6, a.x + v.x, xo.x);
                                xn.y = fmaf(s6, a.y + v.y, xo.y);
                                xn.z = fmaf(s6, a.z + v.z, xo.z);
                                xn.w = fmaf(s6, a.w + v.w, xo.w);
                                dx[q] = xn;
                                __half2 h0 = __floats2half2_rn(xn.x, xn.y);
                                __half2 h1 = __floats2half2_rn(xn.z, xn.w);
                                packed[2*q]   = *reinterpret_cast<uint32_t*>(&h0);
                                packed[2*q+1] = *reinterpret_cast<uint32_t*>(&h1);
                            }
                        }
                        uint4* de = reinterpret_cast<uint4*>(g_xe + off);
                        #pragma unroll
                        for (int q = 0; q < 4; q++) de[q] = reinterpret_cast<uint4*>(packed)[q];
                    }
                }
                TC_FENCE_BEFORE();
                asm volatile("bar.sync 1, 128;" ::: "memory");
                if (wid == 0 && lane == 0) {
                    mbar_arrive_leader(mb_accfree + 8*b);
                    __threadfence();
                    if (ti < 4) atomicAdd(&g_flagH[ev * MT + mi], 1u);
                    else        atomicAdd(&g_flagA[(ev + 1) * MT + mi], 1u);
                }
            }
        }
    }

    __syncthreads();
    if (wid == 0) { TC_RELINQ_CG2(); TC_DEALLOC_CG2(tmem, 512); }
    cluster_sync();

#else  // ---------------- fallback: fp32 FFMA with flags (plain sm_103) ----
    extern __shared__ char smem[];
    float* As = reinterpret_cast<float*>(smem);
    float* Bs = reinterpret_cast<float*>(smem + 8192);

    const int tid = threadIdx.x;
    const int pairId = (int)(blockIdx.x >> 1);
    const int rk = (int)(blockIdx.x & 1);
    const int mi = pairId & (MT - 1);
    const int niBase = pairId >> 4;
    const int tx = tid & 15, ty = tid >> 4;
    const int lr = tid >> 1;
    const int lc = (tid & 1) * 8;
    const int m0 = mi * BMP + rk * 128;

    for (int ev = 0; ev < NEV; ev++) {
        const int e = ev & 3;
        const float wcoef = (e == 1 || e == 2) ? 2.0f : 1.0f;
        const float ccn   = (e == 0 || e == 1) ? 0.5f*dt : (e == 2 ? dt : 0.0f);
        const int first = (e == 0), last = (e == 3);

        for (int ti = 0; ti < 5; ti++) {
            const int g2 = (ti == 4);
            if (ti == 0 && ev > 0) {
                if (tid == 0) flag_wait(&g_flagA[ev * MT + mi], 8);
                __syncthreads();
            }
            if (g2) {
                if (tid == 0) flag_wait(&g_flagH[ev * MT + mi], 32);
                __syncthreads();
            }
            const int K = g2 ? HH : DD;
            const int nout = g2 ? DD : HH;
            const __half* Araw = g2 ? g_h : g_xe;
            const float* Wraw = g2 ? W2raw : W1raw;
            const float* bias = g2 ? b2 : b1;
            const int ni = g2 ? niBase : ((niBase + 4*ti) & (MT - 1));

            for (int half = 0; half < 2; half++) {
                const int n0 = ni * BNP + half * 128;
                float acc[8][8];
                #pragma unroll
                for (int i = 0; i < 8; i++)
                    #pragma unroll
                    for (int jq = 0; jq < 8; jq++) acc[i][jq] = 0.0f;

                for (int k0 = 0; k0 < K; k0 += 16) {
                    {
                        uint4 v = *reinterpret_cast<const uint4*>(Araw + (size_t)(m0 + lr) * K + k0 + lc);
                        const __half* hp = reinterpret_cast<const __half*>(&v);
                        #pragma unroll
                        for (int jq = 0; jq < 8; jq++) As[(lc + jq) * 128 + lr] = __half2float(hp[jq]);
                    }
                    {
                        const float* src = Wraw + (size_t)(n0 + lr) * K + k0 + lc;
                        float4 v1 = reinterpret_cast<const float4*>(src)[0];
                        float4 v2 = reinterpret_cast<const float4*>(src)[1];
                        Bs[(lc + 0) * 128 + lr] = v1.x; Bs[(lc + 1) * 128 + lr] = v1.y;
                        Bs[(lc + 2) * 128 + lr] = v1.z; Bs[(lc + 3) * 128 + lr] = v1.w;
                        Bs[(lc + 4) * 128 + lr] = v2.x; Bs[(lc + 5) * 128 + lr] = v2.y;
                        Bs[(lc + 6) * 128 + lr] = v2.z; Bs[(lc + 7) * 128 + lr] = v2.w;
                    }
                    __syncthreads();
                    #pragma unroll
                    for (int kk = 0; kk < 16; kk++) {
                        float a[8], bb[8];
                        #pragma unroll
                        for (int i = 0; i < 8; i++) a[i] = As[kk * 128 + ty * 8 + i];
                        #pragma unroll
                        for (int jq = 0; jq < 8; jq++) bb[jq] = Bs[kk * 128 + tx * 8 + jq];
                        #pragma unroll
                        for (int i = 0; i < 8; i++)
                            #pragma unroll
                            for (int jq = 0; jq < 8; jq++) acc[i][jq] = fmaf(a[i], bb[jq], acc[i][jq]);
                    }
                    __syncthreads();
                }

                #pragma unroll
                for (int i = 0; i < 8; i++) {
                    int mm = m0 + ty * 8 + i;
                    #pragma unroll
                    for (int jq = 0; jq < 8; jq++) {
                        int n = n0 + tx * 8 + jq;
                        float v = acc[i][jq] + bias[n];
                        size_t o = (size_t)mm * nout + n;
                        if (!g2) {
                            g_h[o] = __float2half_rn(tanh_fast(v));
                        } else if (!last) {
                            float a = first ? v : fmaf(wcoef, v, g_acc[o]);
                            g_acc[o] = a;
                            g_xe[o] = __float2half_rn(fmaf(ccn, v, xc[o]));
                        } else {
                            float xn = fmaf(s6, g_acc[o] + v, xc[o]);
                            xc[o] = xn;
                            g_xe[o] = __float2half_rn(xn);
                        }
                    }
                }
                __syncthreads();
            }
            __threadfence();
            if (tid == 0) {
                if (!g2) atomicAdd(&g_flagH[ev * MT + mi], 1u);
                else     atomicAdd(&g_flagA[(ev + 1) * MT + mi], 1u);
            }
            __syncthreads();
        }
    }
#endif
}

// --------------------------- setup kernels --------------------------------
__global__ void wconv_kernel(const float* __restrict__ W, __half* __restrict__ Wh, int n)
{
    int i = blockIdx.x * blockDim.x + threadIdx.x;
    if (i < n) Wh[i] = __float2half_rn(W[i]);
}

__global__ void prep_kernel(const float* __restrict__ xcin, __half* __restrict__ xe, int n)
{
    int i = blockIdx.x * blockDim.x + threadIdx.x;
    if (i < n) xe[i] = __float2half_rn(xcin[i]);
}

__global__ void zero_flags_kernel()
{
    int i = blockIdx.x * blockDim.x + threadIdx.x;
    if (i < (NEV + 1) * MT) g_flagA[i] = 0u;
    if (i < NEV * MT)       g_flagH[i] = 0u;
}

// ------------------------------- host side --------------------------------
typedef CUresult (*EncodeTiledFn)(
    CUtensorMap*, CUtensorMapDataType, cuuint32_t, void*,
    const cuuint64_t*, const cuuint64_t*, const cuuint32_t*, const cuuint32_t*,
    CUtensorMapInterleave, CUtensorMapSwizzle, CUtensorMapL2promotion, CUtensorMapFloatOOBfill);

static void encode_2d_f16(EncodeTiledFn fn, CUtensorMap* m, void* ptr,
                          uint64_t d0, uint64_t d1)
{
    if (!fn) return;
    cuuint64_t dims[2]    = {d0, d1};
    cuuint64_t strides[1] = {d0 * 2};
    cuuint32_t box[2]     = {BK, 128};
    cuuint32_t es[2]      = {1, 1};
    fn(m, CU_TENSOR_MAP_DATA_TYPE_FLOAT16, 2, ptr, dims, strides, box, es,
       CU_TENSOR_MAP_INTERLEAVE_NONE, CU_TENSOR_MAP_SWIZZLE_128B,
       CU_TENSOR_MAP_L2_PROMOTION_L2_128B, CU_TENSOR_MAP_FLOAT_OOB_FILL_NONE);
}

extern "C" void kernel_launch(void* const* d_in, const int* in_sizes, int n_in,
                              void* d_out, int out_size)
{
    const float* x  = (const float*)d_in[0];
    const float* W1 = (const float*)d_in[1];
    const float* b1 = (const float*)d_in[2];
    const float* W2 = (const float*)d_in[3];
    const float* b2 = (const float*)d_in[4];
    float* xc = (float*)d_out;

    void *pW1h, *pW2h, *pxe, *ph;
    cudaGetSymbolAddress(&pW1h, g_W1h);
    cudaGetSymbolAddress(&pW2h, g_W2h);
    cudaGetSymbolAddress(&pxe,  g_xe);
    cudaGetSymbolAddress(&ph,   g_h);

    EncodeTiledFn encode_fn = nullptr;
    cudaDriverEntryPointQueryResult qres;
    cudaGetDriverEntryPoint("cuTensorMapEncodeTiled", (void**)&encode_fn,
                            cudaEnableDefault, &qres);

    cudaFuncSetAttribute(ode_mega_kernel, cudaFuncAttributeMaxDynamicSharedMemorySize, SMEM_REQ);

    alignas(64) CUtensorMap tmA1, tmB1, tmA2, tmB2;
    memset(&tmA1, 0, sizeof(tmA1)); memset(&tmB1, 0, sizeof(tmB1));
    memset(&tmA2, 0, sizeof(tmA2)); memset(&tmB2, 0, sizeof(tmB2));
    encode_2d_f16(encode_fn, &tmA1, pxe,  DD, BB);
    encode_2d_f16(encode_fn, &tmB1, pW1h, DD, HH);
    encode_2d_f16(encode_fn, &tmA2, ph,   HH, BB);
    encode_2d_f16(encode_fn, &tmB2, pW2h, HH, DD);

    const int nelem = BB * DD;
    const int EB = 256;

    cudaMemcpyAsync(xc, x, (size_t)nelem * sizeof(float), cudaMemcpyDeviceToDevice);
    prep_kernel<<<(nelem + EB - 1)/EB, EB>>>(xc, (__half*)pxe, nelem);
    wconv_kernel<<<(HH*DD + EB - 1)/EB, EB>>>(W1, (__half*)pW1h, HH*DD);
    wconv_kernel<<<(DD*HH + EB - 1)/EB, EB>>>(W2, (__half*)pW2h, DD*HH);
    zero_flags_kernel<<<((NEV + 1) * MT + EB - 1)/EB, EB>>>();

    ode_mega_kernel<<<GRIDC, 256, SMEM_REQ>>>(
        tmA1, tmB1, tmA2, tmB2, b1, b2, xc, W1, W2);

    (void)in_sizes; (void)n_in; (void)out_size;
}

// round 14
// speedup vs baseline: 1.3790x; 1.3790x over previous
#include <cuda_runtime.h>
#include <cuda.h>
#include <cuda_fp16.h>
#include <cstdint>
#include <cstddef>
#include <cstring>

// ----------------------------- problem sizes ------------------------------
#define BB 4096
#define DD 1024
#define HH 4096
#define NSTEPS 64
#define NEV (NSTEPS*4)        // 256 RHS evaluations

// ------------------------------ GEMM tiling -------------------------------
#define BMP 256               // pair M (128 rows per CTA)
#define BNP 256               // pair N (128 B-rows per CTA)
#define BK 64                 // fp16 per K-chunk = 128 B (SW128 atom)
#define STAGES 6
#define TILE_BYTES 16384
#define CHUNK_BYTES (2*TILE_BYTES)
#define PAIR_CHUNK_BYTES (2*CHUNK_BYTES)
#define SMEM_REQ (STAGES*CHUNK_BYTES + 2048)
#define NPAIRS 64
#define GRIDC (2*NPAIRS)
#define MT 16

#define G1_NCH (DD/BK)        // 16
#define G2_NCH (HH/BK)        // 64

// idesc kind::f16 cg2: dtype=F32(1<<4), a/btype=F16, N=256, M=256
#define IDESC_CG2 ((1u<<4) | (32u<<17) | (16u<<24))

#if defined(__CUDA_ARCH__) && (defined(__CUDA_ARCH_FEAT_SM103_ALL) || defined(__CUDA_ARCH_FEAT_SM100_ALL) || defined(__CUDA_ARCH_FEAT_SM101_ALL))
#define HAS_TCGEN05 1
#else
#define HAS_TCGEN05 0
#endif

// --------------------------- persistent scratch ---------------------------
__device__ __align__(1024) __half g_W1h[(size_t)HH * DD];
__device__ __align__(1024) __half g_W2h[(size_t)DD * HH];
__device__ __align__(1024) __half g_xe [(size_t)BB * DD];
__device__ __align__(1024) __half g_h  [(size_t)BB * HH];
__device__ __align__(1024) float  g_acc[(size_t)BB * DD];
__device__ unsigned int g_bar[NEV];              // per-eval global barrier counters
__device__ unsigned int g_flagH[NEV * MT];       // h row-block ready (target 32)

__device__ __forceinline__ float tanh_fast(float x) {
    float y; asm("tanh.approx.f32 %0, %1;" : "=f"(y) : "f"(x)); return y;
}

__device__ __forceinline__ void flag_wait(unsigned int* f, unsigned int tgt) {
    for (int i = 0; i < 4000000; i++) {
        unsigned int v;
        asm volatile("ld.acquire.gpu.u32 %0, [%1];" : "=r"(v) : "l"(f));
        if (v >= tgt) return;
    }
}

// device-wide barrier: one fresh counter per eval
__device__ __forceinline__ void grid_barrier(int ev) {
    __syncthreads();
    if (threadIdx.x == 0) {
        __threadfence();
#if HAS_TCGEN05
        asm volatile("fence.proxy.async;" ::: "memory");
#endif
        unsigned int* c = &g_bar[ev];
        atomicAdd(c, 1u);
        for (int i = 0; i < 2000000; i++) {
            unsigned int v;
            asm volatile("ld.acquire.gpu.u32 %0, [%1];" : "=r"(v) : "l"(c));
            if (v >= (unsigned)GRIDC) break;
        }
    }
    __syncthreads();
}

#if HAS_TCGEN05
// ------------------------------ PTX helpers -------------------------------
__device__ __forceinline__ uint32_t smem_u32(const void* p) {
    uint32_t a;
    asm("{ .reg .u64 t; cvta.to.shared.u64 t, %1; cvt.u32.u64 %0, t; }" : "=r"(a) : "l"(p));
    return a;
}
__device__ __forceinline__ uint32_t ctarank() {
    uint32_t r; asm("mov.u32 %0, %%cluster_ctarank;" : "=r"(r)); return r;
}
__device__ __forceinline__ void cluster_sync() {
    asm volatile("barrier.cluster.arrive.aligned;" ::: "memory");
    asm volatile("barrier.cluster.wait.aligned;" ::: "memory");
}
__device__ __forceinline__ void mbar_init(uint32_t mbar, uint32_t count) {
    asm volatile("mbarrier.init.shared.b64 [%0], %1;" :: "r"(mbar), "r"(count) : "memory");
}
__device__ __forceinline__ void mbar_expect_tx(uint32_t mbar, uint32_t bytes) {
    asm volatile("mbarrier.arrive.expect_tx.shared.b64 _, [%0], %1;" :: "r"(mbar), "r"(bytes) : "memory");
}
__device__ __forceinline__ void mbar_wait(uint32_t mbar, uint32_t parity) {
    for (int i = 0; i < 4000000; i++) {
        uint32_t done;
        asm volatile(
            "{\n\t.reg .pred P;\n\t"
            "mbarrier.try_wait.parity.acquire.cta.shared::cta.b64 P, [%1], %2;\n\t"
            "selp.b32 %0, 1, 0, P;\n\t}"
            : "=r"(done) : "r"(mbar), "r"(parity) : "memory");
        if (done) return;
    }
}
__device__ __forceinline__ void mbar_arrive_leader(uint32_t mbar) {
    uint32_t la = mbar & 0xFEFFFFFFu;
    asm volatile("mbarrier.arrive.shared::cluster.b64 _, [%0];" :: "r"(la) : "memory");
}
__device__ __forceinline__ void tma_load_2d_cg2(uint32_t smem_dst, const CUtensorMap* map,
                                                int32_t cx, int32_t cy, uint32_t mbar) {
    uint32_t lb = mbar & 0xFEFFFFFFu;
    asm volatile(
        "cp.async.bulk.tensor.2d.cta_group::2.shared::cluster.global.tile.mbarrier::complete_tx::bytes "
        "[%0], [%1, {%2, %3}], [%4];"
        :: "r"(smem_dst), "l"(map), "r"(cx), "r"(cy), "r"(lb) : "memory");
}
__device__ __forceinline__ uint64_t make_desc(uint32_t addr) {
    const uint64_t base = (uint64_t(2) << 61) | (uint64_t(1) << 46) |
                          (uint64_t(64) << 32) | (uint64_t(1) << 16);
    return base | ((uint64_t)(addr >> 4) & 0x3FFF);
}
__device__ __forceinline__ void mma_f16_ss_cg2(uint32_t d_tmem, uint64_t a_desc, uint64_t b_desc,
                                               uint32_t idesc, uint32_t enable) {
    asm volatile(
        "{\n\t.reg .pred p;\n\t"
        "setp.ne.u32 p, %5, 0;\n\t"
        "tcgen05.mma.cta_group::2.kind::f16 [%0], %1, %2, %3, "
        "{%4, %4, %4, %4, %4, %4, %4, %4}, p;\n\t}"
        :: "r"(d_tmem), "l"(a_desc), "l"(b_desc), "r"(idesc), "r"(0u), "r"(enable) : "memory");
}
__device__ __forceinline__ void tc_commit_mc2(uint32_t mbar) {
    asm volatile(
        "tcgen05.commit.cta_group::2.mbarrier::arrive::one.shared::cluster.multicast::cluster.b64 [%0], %1;"
        :: "r"(mbar), "h"((uint16_t)0x3) : "memory");
}

#define TC_ALLOC_CG2(slot, n)  asm volatile("tcgen05.alloc.cta_group::2.sync.aligned.shared::cta.b32 [%0], %1;" :: "r"(slot), "r"((uint32_t)(n)) : "memory")
#define TC_RELINQ_CG2()        asm volatile("tcgen05.relinquish_alloc_permit.cta_group::2.sync.aligned;")
#define TC_DEALLOC_CG2(t, n)   asm volatile("tcgen05.dealloc.cta_group::2.sync.aligned.b32 %0, %1;" :: "r"(t), "r"((uint32_t)(n)))
#define TC_WAIT_LD()       asm volatile("tcgen05.wait::ld.sync.aligned;" ::: "memory")
#define TC_FENCE_AFTER()   asm volatile("tcgen05.fence::after_thread_sync;" ::: "memory")
#define TC_FENCE_BEFORE()  asm volatile("tcgen05.fence::before_thread_sync;" ::: "memory")

#define LDTM_X32(r, addr) \
    asm volatile( \
        "tcgen05.ld.sync.aligned.32x32b.x32.b32 " \
        "{%0, %1, %2, %3, %4, %5, %6, %7, " \
        " %8, %9, %10, %11, %12, %13, %14, %15, " \
        " %16, %17, %18, %19, %20, %21, %22, %23, " \
        " %24, %25, %26, %27, %28, %29, %30, %31}, [%32];" \
        : "=r"((r)[0]),  "=r"((r)[1]),  "=r"((r)[2]),  "=r"((r)[3]), \
          "=r"((r)[4]),  "=r"((r)[5]),  "=r"((r)[6]),  "=r"((r)[7]), \
          "=r"((r)[8]),  "=r"((r)[9]),  "=r"((r)[10]), "=r"((r)[11]), \
          "=r"((r)[12]), "=r"((r)[13]), "=r"((r)[14]), "=r"((r)[15]), \
          "=r"((r)[16]), "=r"((r)[17]), "=r"((r)[18]), "=r"((r)[19]), \
          "=r"((r)[20]), "=r"((r)[21]), "=r"((r)[22]), "=r"((r)[23]), \
          "=r"((r)[24]), "=r"((r)[25]), "=r"((r)[26]), "=r"((r)[27]), \
          "=r"((r)[28]), "=r"((r)[29]), "=r"((r)[30]), "=r"((r)[31]) \
        : "r"(addr))
#endif  // HAS_TCGEN05

// ------------------------------- megakernel -------------------------------
// One launch runs all 256 evals. Per eval, pair p (mi=p&15, niBase=p>>4) does
// 4 GEMM1 tiles (ni = niBase+4k) then 1 GEMM2 tile (mi, niBase).
// GEMM1->GEMM2 handoff inside the eval via g_flagH (producer-only wait);
// one device-wide barrier per eval handles all cross-eval dependencies.
__global__ void __launch_bounds__(256, 1) __cluster_dims__(2, 1, 1) ode_mega_kernel(
    const __grid_constant__ CUtensorMap tmA1,
    const __grid_constant__ CUtensorMap tmB1,
    const __grid_constant__ CUtensorMap tmA2,
    const __grid_constant__ CUtensorMap tmB2,
    const float* __restrict__ b1,
    const float* __restrict__ b2,
    float* __restrict__ xc,
    const float* __restrict__ W1raw,
    const float* __restrict__ W2raw)
{
    const float dt = 1.0f / (float)NSTEPS;
    const float s6 = dt / 6.0f;

#if HAS_TCGEN05
    extern __shared__ char smem[];
    uint32_t sbase = smem_u32(smem);
    uint32_t tile0 = (sbase + 1023u) & ~1023u;
    uint32_t ctrl  = tile0 + STAGES * CHUNK_BYTES;
    uint32_t mb_full    = ctrl;
    uint32_t mb_empty   = ctrl + 64;
    uint32_t mb_accfull = ctrl + 128;
    uint32_t mb_accfree = ctrl + 160;
    uint32_t tmem_slot  = ctrl + 192;

    const int tid = threadIdx.x, wid = tid >> 5, lane = tid & 31;
    const uint32_t rank = ctarank();
    const int pairId = (int)(blockIdx.x >> 1);
    const int mi     = pairId & (MT - 1);
    const int niBase = pairId >> 4;          // 0..3

    if (wid == 0) { TC_ALLOC_CG2(tmem_slot, 512); }
    if (tid == 0) {
        for (int s = 0; s < STAGES; s++) {
            mbar_init(mb_full  + 8*s, 1);
            mbar_init(mb_empty + 8*s, 1);
        }
        mbar_init(mb_accfull + 0, 1);  mbar_init(mb_accfull + 8, 1);
        mbar_init(mb_accfree + 0, 2);  mbar_init(mb_accfree + 8, 2);
    }
    __syncthreads();
    cluster_sync();

    uint32_t tmem;
    asm volatile("ld.shared.b32 %0, [%1];" : "=r"(tmem) : "r"(tmem_slot));

    // persistent per-role state (flows across evals)
    int pr_s = 0;  uint32_t pr_ph = 1;   // producer stage/phase
    int mm_s = 0;  uint32_t mm_ph = 0;   // MMA stage/phase
    int mm_j = 0;                        // MMA global tile counter
    int ep_j = 0;                        // epilogue global tile counter

    const int mself = mi * BMP + (int)rank * 128;

    for (int ev = 0; ev < NEV; ev++) {
        const int e = ev & 3;
        const float wcoef = (e == 1 || e == 2) ? 2.0f : 1.0f;
        const float ccn   = (e == 0 || e == 1) ? 0.5f*dt : (e == 2 ? dt : 0.0f);
        const int first = (e == 0), last = (e == 3);

        // ---- producer: warp 4 lane 0, BOTH CTAs ----
        if (wid == 4 && lane == 0) {
            // GEMM1: xe is safe (eval barrier passed)
            for (int k4 = 0; k4 < 4; k4++) {
                const int ni = niBase + 4*k4;
                const int nself = ni * BNP + (int)rank * 128;
                for (int c = 0; c < G1_NCH; c++) {
                    mbar_wait(mb_empty + 8*pr_s, pr_ph);
                    uint32_t st = tile0 + pr_s * CHUNK_BYTES;
                    if (rank == 0) mbar_expect_tx(mb_full + 8*pr_s, PAIR_CHUNK_BYTES);
                    tma_load_2d_cg2(st,              &tmA1, c*BK, mself, mb_full + 8*pr_s);
                    tma_load_2d_cg2(st + TILE_BYTES, &tmB1, c*BK, nself, mb_full + 8*pr_s);
                    if (++pr_s == STAGES) { pr_s = 0; pr_ph ^= 1; }
                }
            }
            // GEMM2: A = h[mi block] -- needs the 16 GEMM1 (mi,*) tiles (4 pairs)
            flag_wait(&g_flagH[ev * MT + mi], 32);
            asm volatile("fence.proxy.async;" ::: "memory");
            {
                const int nself = niBase * BNP + (int)rank * 128;
                for (int c = 0; c < G2_NCH; c++) {
                    mbar_wait(mb_empty + 8*pr_s, pr_ph);
                    uint32_t st = tile0 + pr_s * CHUNK_BYTES;
                    if (rank == 0) mbar_expect_tx(mb_full + 8*pr_s, PAIR_CHUNK_BYTES);
                    tma_load_2d_cg2(st,              &tmA2, c*BK, mself, mb_full + 8*pr_s);
                    tma_load_2d_cg2(st + TILE_BYTES, &tmB2, c*BK, nself, mb_full + 8*pr_s);
                    if (++pr_s == STAGES) { pr_s = 0; pr_ph ^= 1; }
                }
            }
        }

        // ---- MMA issuer: warp 5 lane 0, LEADER only ----
        if (rank == 0 && wid == 5 && lane == 0) {
            for (int ti = 0; ti < 5; ti++, mm_j++) {
                const int nch = (ti < 4) ? G1_NCH : G2_NCH;
                const uint32_t b = (uint32_t)(mm_j & 1);
                const uint32_t dtm = tmem + b * 256;
                if (mm_j >= 2) { mbar_wait(mb_accfree + 8*b, (uint32_t)(((mm_j - 2) >> 1) & 1)); TC_FENCE_AFTER(); }
                uint32_t en = 0;
                for (int c = 0; c < nch; c++) {
                    mbar_wait(mb_full + 8*mm_s, mm_ph);
                    uint32_t st = tile0 + mm_s * CHUNK_BYTES;
                    uint64_t da = make_desc(st);
                    uint64_t db = make_desc(st + TILE_BYTES);
                    #pragma unroll
                    for (int k = 0; k < 4; k++) { mma_f16_ss_cg2(dtm, da + 2*k, db + 2*k, IDESC_CG2, en); en = 1; }
                    tc_commit_mc2(mb_empty + 8*mm_s);
                    if (++mm_s == STAGES) { mm_s = 0; mm_ph ^= 1; }
                }
                tc_commit_mc2(mb_accfull + 8*b);
            }
        }

        // ---- epilogue: warps 0-3, BOTH CTAs ----
        if (wid < 4) {
            const int m = mself + wid * 32 + lane;
            for (int ti = 0; ti < 5; ti++, ep_j++) {
                const uint32_t b = (uint32_t)(ep_j & 1);
                mbar_wait(mb_accfull + 8*b, (uint32_t)((ep_j >> 1) & 1));
                TC_FENCE_AFTER();
                if (ti < 4) {
                    const int ni = niBase + 4*ti;
                    const int n0 = ni * BNP;
                    for (int nb = 0; nb < 8; nb++) {
                        uint32_t rh[32];
                        LDTM_X32(rh, tmem + b * 256 + nb * 32);
                        TC_WAIT_LD();
                        const int nc = n0 + nb * 32;
                        uint32_t packed[16];
                        #pragma unroll
                        for (int q = 0; q < 16; q++) {
                            float v0 = __uint_as_float(rh[2*q])   + b1[nc + 2*q];
                            float v1 = __uint_as_float(rh[2*q+1]) + b1[nc + 2*q+1];
                            __half2 h2 = __floats2half2_rn(tanh_fast(v0), tanh_fast(v1));
                            packed[q] = *reinterpret_cast<uint32_t*>(&h2);
                        }
                        uint4* dst = reinterpret_cast<uint4*>(g_h + (size_t)m * HH + nc);
                        #pragma unroll
                        for (int q = 0; q < 4; q++) dst[q] = reinterpret_cast<uint4*>(packed)[q];
                    }
                } else {
                    const int n0 = niBase * BNP;
                    for (int nb = 0; nb < 8; nb++) {
                        uint32_t rh[32];
                        LDTM_X32(rh, tmem + b * 256 + nb * 32);
                        TC_WAIT_LD();
                        const int nc = n0 + nb * 32;
                        float vals[32];
                        #pragma unroll
                        for (int q = 0; q < 32; q++)
                            vals[q] = __uint_as_float(rh[q]) + b2[nc + q];
                        const size_t off = (size_t)m * DD + nc;
                        uint32_t packed[16];
                        if (!last) {
                            float4* da = reinterpret_cast<float4*>(g_acc + off);
                            const float4* dx = reinterpret_cast<const float4*>(xc + off);
                            #pragma unroll
                            for (int q = 0; q < 8; q++) {
                                float4 v = reinterpret_cast<float4*>(vals)[q];
                                float4 a;
                                if (first) { a = v; }
                                else {
                                    a = da[q];
                                    a.x += wcoef * v.x; a.y += wcoef * v.y;
                                    a.z += wcoef * v.z; a.w += wcoef * v.w;
                                }
                                da[q] = a;
                                float4 xo = dx[q];
                                __half2 h0 = __floats2half2_rn(fmaf(ccn, v.x, xo.x), fmaf(ccn, v.y, xo.y));
                                __half2 h1 = __floats2half2_rn(fmaf(ccn, v.z, xo.z), fmaf(ccn, v.w, xo.w));
                                packed[2*q]   = *reinterpret_cast<uint32_t*>(&h0);
                                packed[2*q+1] = *reinterpret_cast<uint32_t*>(&h1);
                            }
                        } else {
                            const float4* da = reinterpret_cast<const float4*>(g_acc + off);
                            float4* dx = reinterpret_cast<float4*>(xc + off);
                            #pragma unroll
                            for (int q = 0; q < 8; q++) {
                                float4 v = reinterpret_cast<float4*>(vals)[q];
                                float4 a = da[q];
                                float4 xo = dx[q];
                                float4 xn;
                                xn.x = fmaf(s6, a.x + v.x, xo.x);
                                xn.y = fmaf(s6, a.y + v.y, xo.y);
                                xn.z = fmaf(s6, a.z + v.z, xo.z);
                                xn.w = fmaf(s6, a.w + v.w, xo.w);
                                dx[q] = xn;
                                __half2 h0 = __floats2half2_rn(xn.x, xn.y);
                                __half2 h1 = __floats2half2_rn(xn.z, xn.w);
                                packed[2*q]   = *reinterpret_cast<uint32_t*>(&h0);
                                packed[2*q+1] = *reinterpret_cast<uint32_t*>(&h1);
                            }
                        }
                        uint4* de = reinterpret_cast<uint4*>(g_xe + off);
                        #pragma unroll
                        for (int q = 0; q < 4; q++) de[q] = reinterpret_cast<uint4*>(packed)[q];
                    }
                }
                TC_FENCE_BEFORE();
                asm volatile("bar.sync 1, 128;" ::: "memory");
                if (wid == 0 && lane == 0) {
                    mbar_arrive_leader(mb_accfree + 8*b);
                    if (ti < 4) {
                        __threadfence();
                        atomicAdd(&g_flagH[ev * MT + mi], 1u);
                    }
                }
            }
        }

        grid_barrier(ev);
    }

    __syncthreads();
    if (wid == 0) { TC_RELINQ_CG2(); TC_DEALLOC_CG2(tmem, 512); }
    cluster_sync();

#else  // ---------------- fallback: fp32 FFMA (plain sm_103) ----
    extern __shared__ char smem[];
    float* As = reinterpret_cast<float*>(smem);
    float* Bs = reinterpret_cast<float*>(smem + 8192);

    const int tid = threadIdx.x;
    const int pairId = (int)(blockIdx.x >> 1);
    const int rk = (int)(blockIdx.x & 1);
    const int mi = pairId & (MT - 1);
    const int niBase = pairId >> 4;
    const int tx = tid & 15, ty = tid >> 4;
    const int lr = tid >> 1;
    const int lc = (tid & 1) * 8;
    const int m0 = mi * BMP + rk * 128;

    for (int ev = 0; ev < NEV; ev++) {
        const int e = ev & 3;
        const float wcoef = (e == 1 || e == 2) ? 2.0f : 1.0f;
        const float ccn   = (e == 0 || e == 1) ? 0.5f*dt : (e == 2 ? dt : 0.0f);
        const int first = (e == 0), last = (e == 3);

        for (int ti = 0; ti < 5; ti++) {
            const int g2 = (ti == 4);
            if (g2) {
                if (tid == 0) flag_wait(&g_flagH[ev * MT + mi], 32);
                __syncthreads();
            }
            const int K = g2 ? HH : DD;
            const int nout = g2 ? DD : HH;
            const __half* Araw = g2 ? g_h : g_xe;
            const float* Wraw = g2 ? W2raw : W1raw;
            const float* bias = g2 ? b2 : b1;
            const int ni = g2 ? niBase : (niBase + 4*ti);

            for (int half = 0; half < 2; half++) {
                const int n0 = ni * BNP + half * 128;
                float acc[8][8];
                #pragma unroll
                for (int i = 0; i < 8; i++)
                    #pragma unroll
                    for (int jq = 0; jq < 8; jq++) acc[i][jq] = 0.0f;

                for (int k0 = 0; k0 < K; k0 += 16) {
                    {
                        uint4 v = *reinterpret_cast<const uint4*>(Araw + (size_t)(m0 + lr) * K + k0 + lc);
                        const __half* hp = reinterpret_cast<const __half*>(&v);
                        #pragma unroll
                        for (int jq = 0; jq < 8; jq++) As[(lc + jq) * 128 + lr] = __half2float(hp[jq]);
                    }
                    {
                        const float* src = Wraw + (size_t)(n0 + lr) * K + k0 + lc;
                        float4 v1 = reinterpret_cast<const float4*>(src)[0];
                        float4 v2 = reinterpret_cast<const float4*>(src)[1];
                        Bs[(lc + 0) * 128 + lr] = v1.x; Bs[(lc + 1) * 128 + lr] = v1.y;
                        Bs[(lc + 2) * 128 + lr] = v1.z; Bs[(lc + 3) * 128 + lr] = v1.w;
                        Bs[(lc + 4) * 128 + lr] = v2.x; Bs[(lc + 5) * 128 + lr] = v2.y;
                        Bs[(lc + 6) * 128 + lr] = v2.z; Bs[(lc + 7) * 128 + lr] = v2.w;
                    }
                    __syncthreads();
                    #pragma unroll
                    for (int kk = 0; kk < 16; kk++) {
                        float a[8], bb[8];
                        #pragma unroll
                        for (int i = 0; i < 8; i++) a[i] = As[kk * 128 + ty * 8 + i];
                        #pragma unroll
                        for (int jq = 0; jq < 8; jq++) bb[jq] = Bs[kk * 128 + tx * 8 + jq];
                        #pragma unroll
                        for (int i = 0; i < 8; i++)
                            #pragma unroll
                            for (int jq = 0; jq < 8; jq++) acc[i][jq] = fmaf(a[i], bb[jq], acc[i][jq]);
                    }
                    __syncthreads();
                }

                #pragma unroll
                for (int i = 0; i < 8; i++) {
                    int mm = m0 + ty * 8 + i;
                    #pragma unroll
                    for (int jq = 0; jq < 8; jq++) {
                        int n = n0 + tx * 8 + jq;
                        float v = acc[i][jq] + bias[n];
                        size_t o = (size_t)mm * nout + n;
                        if (!g2) {
                            g_h[o] = __float2half_rn(tanh_fast(v));
                        } else if (!last) {
                            float a = first ? v : fmaf(wcoef, v, g_acc[o]);
                            g_acc[o] = a;
                            g_xe[o] = __float2half_rn(fmaf(ccn, v, xc[o]));
                        } else {
                            float xn = fmaf(s6, g_acc[o] + v, xc[o]);
                            xc[o] = xn;
                            g_xe[o] = __float2half_rn(xn);
                        }
                    }
                }
                __syncthreads();
            }
            if (!g2) {
                __threadfence();
                if (tid == 0) atomicAdd(&g_flagH[ev * MT + mi], 1u);
                __syncthreads();
            }
        }
        grid_barrier(ev);
    }
#endif
}

// --------------------------- setup kernels --------------------------------
__global__ void wconv_kernel(const float* __restrict__ W, __half* __restrict__ Wh, int n)
{
    int i = blockIdx.x * blockDim.x + threadIdx.x;
    if (i < n) Wh[i] = __float2half_rn(W[i]);
}

__global__ void prep_kernel(const float* __restrict__ xcin, __half* __restrict__ xe, int n)
{
    int i = blockIdx.x * blockDim.x + threadIdx.x;
    if (i < n) xe[i] = __float2half_rn(xcin[i]);
}

__global__ void zero_sync_kernel()
{
    int i = blockIdx.x * blockDim.x + threadIdx.x;
    if (i < NEV)      g_bar[i] = 0u;
    if (i < NEV * MT) g_flagH[i] = 0u;
}

// ------------------------------- host side --------------------------------
typedef CUresult (*EncodeTiledFn)(
    CUtensorMap*, CUtensorMapDataType, cuuint32_t, void*,
    const cuuint64_t*, const cuuint64_t*, const cuuint32_t*, const cuuint32_t*,
    CUtensorMapInterleave, CUtensorMapSwizzle, CUtensorMapL2promotion, CUtensorMapFloatOOBfill);

static void encode_2d_f16(EncodeTiledFn fn, CUtensorMap* m, void* ptr,
                          uint64_t d0, uint64_t d1)
{
    if (!fn) return;
    cuuint64_t dims[2]    = {d0, d1};
    cuuint64_t strides[1] = {d0 * 2};
    cuuint32_t box[2]     = {BK, 128};
    cuuint32_t es[2]      = {1, 1};
    fn(m, CU_TENSOR_MAP_DATA_TYPE_FLOAT16, 2, ptr, dims, strides, box, es,
       CU_TENSOR_MAP_INTERLEAVE_NONE, CU_TENSOR_MAP_SWIZZLE_128B,
       CU_TENSOR_MAP_L2_PROMOTION_L2_128B, CU_TENSOR_MAP_FLOAT_OOB_FILL_NONE);
}

extern "C" void kernel_launch(void* const* d_in, const int* in_sizes, int n_in,
                              void* d_out, int out_size)
{
    const float* x  = (const float*)d_in[0];
    const float* W1 = (const float*)d_in[1];
    const float* b1 = (const float*)d_in[2];
    const float* W2 = (const float*)d_in[3];
    const float* b2 = (const float*)d_in[4];
    float* xc = (float*)d_out;

    void *pW1h, *pW2h, *pxe, *ph;
    cudaGetSymbolAddress(&pW1h, g_W1h);
    cudaGetSymbolAddress(&pW2h, g_W2h);
    cudaGetSymbolAddress(&pxe,  g_xe);
    cudaGetSymbolAddress(&ph,   g_h);

    EncodeTiledFn encode_fn = nullptr;
    cudaDriverEntryPointQueryResult qres;
    cudaGetDriverEntryPoint("cuTensorMapEncodeTiled", (void**)&encode_fn,
                            cudaEnableDefault, &qres);

    cudaFuncSetAttribute(ode_mega_kernel, cudaFuncAttributeMaxDynamicSharedMemorySize, SMEM_REQ);

    alignas(64) CUtensorMap tmA1, tmB1, tmA2, tmB2;
    memset(&tmA1, 0, sizeof(tmA1)); memset(&tmB1, 0, sizeof(tmB1));
    memset(&tmA2, 0, sizeof(tmA2)); memset(&tmB2, 0, sizeof(tmB2));
    encode_2d_f16(encode_fn, &tmA1, pxe,  DD, BB);
    encode_2d_f16(encode_fn, &tmB1, pW1h, DD, HH);
    encode_2d_f16(encode_fn, &tmA2, ph,   HH, BB);
    encode_2d_f16(encode_fn, &tmB2, pW2h, HH, DD);

    const int nelem = BB * DD;
    const int EB = 256;

    cudaMemcpyAsync(xc, x, (size_t)nelem * sizeof(float), cudaMemcpyDeviceToDevice);
    prep_kernel<<<(nelem + EB - 1)/EB, EB>>>(xc, (__half*)pxe, nelem);
    wconv_kernel<<<(HH*DD + EB - 1)/EB, EB>>>(W1, (__half*)pW1h, HH*DD);
    wconv_kernel<<<(DD*HH + EB - 1)/EB, EB>>>(W2, (__half*)pW2h, DD*HH);
    zero_sync_kernel<<<(NEV * MT + EB - 1)/EB, EB>>>();

    ode_mega_kernel<<<GRIDC, 256, SMEM_REQ>>>(
        tmA1, tmB1, tmA2, tmB2, b1, b2, xc, W1, W2);

    (void)in_sizes; (void)n_in; (void)out_size;
}

// round 17
// speedup vs baseline: 1.3931x; 1.0103x over previous
#include <cuda_runtime.h>
#include <cuda.h>
#include <cuda_fp16.h>
#include <cstdint>
#include <cstddef>
#include <cstring>

// ----------------------------- problem sizes ------------------------------
#define BB 4096   // batch
#define DD 1024   // input dim
#define HH 4096   // hidden dim
#define NSTEPS 64
#define NPH (NSTEPS*8)        // 512 phases: (step, eval, gemm1|gemm2)

// ------------------------------ GEMM tiling -------------------------------
#define BMP 256               // pair M (128 rows per CTA)
#define BNP 256               // pair N (128 B-rows per CTA)
#define BK 64                 // fp16 per K-chunk = 128 B (SW128 atom)
#define STAGES 6
#define TILE_BYTES 16384      // 128 rows * 128 B
#define CHUNK_BYTES (2*TILE_BYTES)        // per-CTA: A(16K) + B(16K)
#define PAIR_CHUNK_BYTES (2*CHUNK_BYTES)
#define SMEM_REQ (STAGES*CHUNK_BYTES + 2048)
#define NPAIRS 74             // persistent pairs -> 148 CTAs (full chip)
#define GRIDC (2*NPAIRS)
#define MT 16                 // M pair-tiles = BB/BMP

#define G1_NCH (DD/BK)        // 16
#define G1_NT  ((BB/BMP)*(HH/BNP))  // 256
#define G2_NCH (HH/BK)        // 64
#define G2_NT  ((BB/BMP)*(DD/BNP))  // 64

// idesc kind::f16 cg2: dtype=F32(1<<4), a/btype=F16, N=256, M=256
#define IDESC_CG2 ((1u<<4) | (32u<<17) | (16u<<24))

#if defined(__CUDA_ARCH__) && (defined(__CUDA_ARCH_FEAT_SM103_ALL) || defined(__CUDA_ARCH_FEAT_SM100_ALL) || defined(__CUDA_ARCH_FEAT_SM101_ALL))
#define HAS_TCGEN05 1
#else
#define HAS_TCGEN05 0
#endif

// --------------------------- persistent scratch ---------------------------
__device__ __align__(1024) __half g_W1h[(size_t)HH * DD];
__device__ __align__(1024) __half g_W2h[(size_t)DD * HH];
__device__ __align__(1024) __half g_xe [(size_t)BB * DD];
__device__ __align__(1024) __half g_h  [(size_t)BB * HH];
__device__ __align__(1024) float  g_acc[(size_t)BB * DD];
__device__ unsigned int g_bar[NPH];

__device__ __forceinline__ float tanh_fast(float x) {
    float y; asm("tanh.approx.f32 %0, %1;" : "=f"(y) : "f"(x)); return y;
}

// device-wide barrier: one fresh counter per phase (no sense reversal needed)
__device__ __forceinline__ void grid_barrier(int phase) {
    __syncthreads();
    if (threadIdx.x == 0) {
        __threadfence();
#if HAS_TCGEN05
        asm volatile("fence.proxy.async;" ::: "memory");
#endif
        unsigned int* c = &g_bar[phase];
        atomicAdd(c, 1u);
        for (int i = 0; i < 2000000; i++) {
            unsigned int v;
            asm volatile("ld.acquire.gpu.u32 %0, [%1];" : "=r"(v) : "l"(c));
            if (v >= (unsigned)GRIDC) break;
        }
    }
    __syncthreads();
}

#if HAS_TCGEN05
// ------------------------------ PTX helpers -------------------------------
__device__ __forceinline__ uint32_t smem_u32(const void* p) {
    uint32_t a;
    asm("{ .reg .u64 t; cvta.to.shared.u64 t, %1; cvt.u32.u64 %0, t; }" : "=r"(a) : "l"(p));
    return a;
}
__device__ __forceinline__ uint32_t ctarank() {
    uint32_t r; asm("mov.u32 %0, %%cluster_ctarank;" : "=r"(r)); return r;
}
__device__ __forceinline__ void cluster_sync() {
    asm volatile("barrier.cluster.arrive.aligned;" ::: "memory");
    asm volatile("barrier.cluster.wait.aligned;" ::: "memory");
}
__device__ __forceinline__ void mbar_init(uint32_t mbar, uint32_t count) {
    asm volatile("mbarrier.init.shared.b64 [%0], %1;" :: "r"(mbar), "r"(count) : "memory");
}
__device__ __forceinline__ void mbar_expect_tx(uint32_t mbar, uint32_t bytes) {
    asm volatile("mbarrier.arrive.expect_tx.shared.b64 _, [%0], %1;" :: "r"(mbar), "r"(bytes) : "memory");
}
__device__ __forceinline__ void mbar_wait(uint32_t mbar, uint32_t parity) {
    for (int i = 0; i < 4000000; i++) {
        uint32_t done;
        asm volatile(
            "{\n\t.reg .pred P;\n\t"
            "mbarrier.try_wait.parity.acquire.cta.shared::cta.b64 P, [%1], %2;\n\t"
            "selp.b32 %0, 1, 0, P;\n\t}"
            : "=r"(done) : "r"(mbar), "r"(parity) : "memory");
        if (done) return;
    }
}
__device__ __forceinline__ void mbar_arrive_leader(uint32_t mbar) {
    uint32_t la = mbar & 0xFEFFFFFFu;
    asm volatile("mbarrier.arrive.shared::cluster.b64 _, [%0];" :: "r"(la) : "memory");
}
__device__ __forceinline__ void tma_load_2d_cg2(uint32_t smem_dst, const CUtensorMap* map,
                                                int32_t cx, int32_t cy, uint32_t mbar) {
    uint32_t lb = mbar & 0xFEFFFFFFu;
    asm volatile(
        "cp.async.bulk.tensor.2d.cta_group::2.shared::cluster.global.tile.mbarrier::complete_tx::bytes "
        "[%0], [%1, {%2, %3}], [%4];"
        :: "r"(smem_dst), "l"(map), "r"(cx), "r"(cy), "r"(lb) : "memory");
}
__device__ __forceinline__ uint64_t make_desc(uint32_t addr) {
    const uint64_t base = (uint64_t(2) << 61) | (uint64_t(1) << 46) |
                          (uint64_t(64) << 32) | (uint64_t(1) << 16);
    return base | ((uint64_t)(addr >> 4) & 0x3FFF);
}
__device__ __forceinline__ void mma_f16_ss_cg2(uint32_t d_tmem, uint64_t a_desc, uint64_t b_desc,
                                               uint32_t idesc, uint32_t enable) {
    asm volatile(
        "{\n\t.reg .pred p;\n\t"
        "setp.ne.u32 p, %5, 0;\n\t"
        "tcgen05.mma.cta_group::2.kind::f16 [%0], %1, %2, %3, "
        "{%4, %4, %4, %4, %4, %4, %4, %4}, p;\n\t}"
        :: "r"(d_tmem), "l"(a_desc), "l"(b_desc), "r"(idesc), "r"(0u), "r"(enable) : "memory");
}
__device__ __forceinline__ void tc_commit_mc2(uint32_t mbar) {
    asm volatile(
        "tcgen05.commit.cta_group::2.mbarrier::arrive::one.shared::cluster.multicast::cluster.b64 [%0], %1;"
        :: "r"(mbar), "h"((uint16_t)0x3) : "memory");
}

#define TC_ALLOC_CG2(slot, n)  asm volatile("tcgen05.alloc.cta_group::2.sync.aligned.shared::cta.b32 [%0], %1;" :: "r"(slot), "r"((uint32_t)(n)) : "memory")
#define TC_RELINQ_CG2()        asm volatile("tcgen05.relinquish_alloc_permit.cta_group::2.sync.aligned;")
#define TC_DEALLOC_CG2(t, n)   asm volatile("tcgen05.dealloc.cta_group::2.sync.aligned.b32 %0, %1;" :: "r"(t), "r"((uint32_t)(n)))
#define TC_WAIT_LD()       asm volatile("tcgen05.wait::ld.sync.aligned;" ::: "memory")
#define TC_FENCE_AFTER()   asm volatile("tcgen05.fence::after_thread_sync;" ::: "memory")
#define TC_FENCE_BEFORE()  asm volatile("tcgen05.fence::before_thread_sync;" ::: "memory")

#define LDTM_X32(r, addr) \
    asm volatile( \
        "tcgen05.ld.sync.aligned.32x32b.x32.b32 " \
        "{%0, %1, %2, %3, %4, %5, %6, %7, " \
        " %8, %9, %10, %11, %12, %13, %14, %15, " \
        " %16, %17, %18, %19, %20, %21, %22, %23, " \
        " %24, %25, %26, %27, %28, %29, %30, %31}, [%32];" \
        : "=r"((r)[0]),  "=r"((r)[1]),  "=r"((r)[2]),  "=r"((r)[3]), \
          "=r"((r)[4]),  "=r"((r)[5]),  "=r"((r)[6]),  "=r"((r)[7]), \
          "=r"((r)[8]),  "=r"((r)[9]),  "=r"((r)[10]), "=r"((r)[11]), \
          "=r"((r)[12]), "=r"((r)[13]), "=r"((r)[14]), "=r"((r)[15]), \
          "=r"((r)[16]), "=r"((r)[17]), "=r"((r)[18]), "=r"((r)[19]), \
          "=r"((r)[20]), "=r"((r)[21]), "=r"((r)[22]), "=r"((r)[23]), \
          "=r"((r)[24]), "=r"((r)[25]), "=r"((r)[26]), "=r"((r)[27]), \
          "=r"((r)[28]), "=r"((r)[29]), "=r"((r)[30]), "=r"((r)[31]) \
        : "r"(addr))
#endif  // HAS_TCGEN05

// ------------------------------- megakernel -------------------------------
// One launch runs all 64 RK4 steps. Phase p: step=p>>3, eval=(p>>1)&3,
// g2=p&1. Device-wide barrier between phases. Tile ownership is dynamic
// (t = pairId + j*NPAIRS), so NPAIRS=74 (full chip) needs no other change.
__global__ void __launch_bounds__(256, 1) __cluster_dims__(2, 1, 1) ode_mega_kernel(
    const __grid_constant__ CUtensorMap tmA1,
    const __grid_constant__ CUtensorMap tmB1,
    const __grid_constant__ CUtensorMap tmA2,
    const __grid_constant__ CUtensorMap tmB2,
    const float* __restrict__ b1,
    const float* __restrict__ b2,
    float* __restrict__ xc,
    const float* __restrict__ W1raw,
    const float* __restrict__ W2raw)
{
    const float dt = 1.0f / (float)NSTEPS;
    const float s6 = dt / 6.0f;

#if HAS_TCGEN05
    extern __shared__ char smem[];
    uint32_t sbase = smem_u32(smem);
    uint32_t tile0 = (sbase + 1023u) & ~1023u;
    uint32_t ctrl  = tile0 + STAGES * CHUNK_BYTES;
    uint32_t mb_full    = ctrl;          // STAGES * 8B
    uint32_t mb_empty   = ctrl + 64;     // STAGES * 8B
    uint32_t mb_accfull = ctrl + 128;    // 2 * 8B
    uint32_t mb_accfree = ctrl + 160;    // 2 * 8B (count 2)
    uint32_t tmem_slot  = ctrl + 192;

    const int tid = threadIdx.x, wid = tid >> 5, lane = tid & 31;
    const uint32_t rank = ctarank();
    const int pairId = (int)(blockIdx.x >> 1);

    if (wid == 0) { TC_ALLOC_CG2(tmem_slot, 512); }
    if (tid == 0) {
        for (int s = 0; s < STAGES; s++) {
            mbar_init(mb_full  + 8*s, 1);
            mbar_init(mb_empty + 8*s, 1);
        }
        mbar_init(mb_accfull + 0, 1);  mbar_init(mb_accfull + 8, 1);
        mbar_init(mb_accfree + 0, 2);  mbar_init(mb_accfree + 8, 2);
    }
    __syncthreads();
    cluster_sync();

    uint32_t tmem;
    asm volatile("ld.shared.b32 %0, [%1];" : "=r"(tmem) : "r"(tmem_slot));

    // persistent per-role state (flows across phases)
    int pr_s = 0;  uint32_t pr_ph = 1;   // producer stage/phase
    int mm_s = 0;  uint32_t mm_ph = 0;   // MMA stage/phase
    int mm_j = 0;                        // MMA global tile counter
    int ep_j = 0;                        // epilogue global tile counter

    for (int phase = 0; phase < NPH; phase++) {
        const int e  = (phase >> 1) & 3;
        const int g2 = phase & 1;
        const int nchunks = g2 ? G2_NCH : G1_NCH;
        const int ntiles  = g2 ? G2_NT  : G1_NT;
        const CUtensorMap* mA = g2 ? &tmA2 : &tmA1;
        const CUtensorMap* mB = g2 ? &tmB2 : &tmB1;
        const float* bias = g2 ? b2 : b1;
        const float wcoef = (e == 1 || e == 2) ? 2.0f : 1.0f;
        const float ccn   = (e == 0 || e == 1) ? 0.5f*dt : (e == 2 ? dt : 0.0f);
        const int first = (e == 0), last = (e == 3);
        const int nout = g2 ? DD : HH;

        // ---- producer: warp 4 lane 0, BOTH CTAs ----
        if (wid == 4 && lane == 0) {
            for (int t = pairId; t < ntiles; t += NPAIRS) {
                const int mi = t & (MT - 1), ni = t >> 4;
                const int mself = mi * BMP + (int)rank * 128;
                const int nself = ni * BNP + (int)rank * 128;
                for (int c = 0; c < nchunks; c++) {
                    mbar_wait(mb_empty + 8*pr_s, pr_ph);
                    uint32_t st = tile0 + pr_s * CHUNK_BYTES;
                    if (rank == 0) mbar_expect_tx(mb_full + 8*pr_s, PAIR_CHUNK_BYTES);
                    tma_load_2d_cg2(st,              mA, c*BK, mself, mb_full + 8*pr_s);
                    tma_load_2d_cg2(st + TILE_BYTES, mB, c*BK, nself, mb_full + 8*pr_s);
                    if (++pr_s == STAGES) { pr_s = 0; pr_ph ^= 1; }
                }
            }
        }

        // ---- MMA issuer: warp 5 lane 0, LEADER only ----
        if (rank == 0 && wid == 5 && lane == 0) {
            for (int t = pairId; t < ntiles; t += NPAIRS, mm_j++) {
                const uint32_t b = (uint32_t)(mm_j & 1);
                const uint32_t dtm = tmem + b * 256;
                if (mm_j >= 2) { mbar_wait(mb_accfree + 8*b, (uint32_t)(((mm_j - 2) >> 1) & 1)); TC_FENCE_AFTER(); }
                uint32_t en = 0;
                for (int c = 0; c < nchunks; c++) {
                    mbar_wait(mb_full + 8*mm_s, mm_ph);
                    uint32_t st = tile0 + mm_s * CHUNK_BYTES;
                    uint64_t da = make_desc(st);
                    uint64_t db = make_desc(st + TILE_BYTES);
                    #pragma unroll
                    for (int k = 0; k < 4; k++) { mma_f16_ss_cg2(dtm, da + 2*k, db + 2*k, IDESC_CG2, en); en = 1; }
                    tc_commit_mc2(mb_empty + 8*mm_s);
                    if (++mm_s == STAGES) { mm_s = 0; mm_ph ^= 1; }
                }
                tc_commit_mc2(mb_accfull + 8*b);
            }
        }

        // ---- epilogue: warps 0-3, BOTH CTAs ----
        if (wid < 4) {
            for (int t = pairId; t < ntiles; t += NPAIRS, ep_j++) {
                const uint32_t b = (uint32_t)(ep_j & 1);
                mbar_wait(mb_accfull + 8*b, (uint32_t)((ep_j >> 1) & 1));
                TC_FENCE_AFTER();
                const int mi = t & (MT - 1), ni = t >> 4;
                const int m  = mi * BMP + (int)rank * 128 + wid * 32 + lane;
                const int n0 = ni * BNP;
                for (int nb = 0; nb < 8; nb++) {
                    uint32_t rh[32];
                    LDTM_X32(rh, tmem + b * 256 + nb * 32);
                    TC_WAIT_LD();
                    const int nc = n0 + nb * 32;
                    if (!g2) {
                        uint32_t packed[16];
                        #pragma unroll
                        for (int q = 0; q < 16; q++) {
                            float v0 = __uint_as_float(rh[2*q])   + bias[nc + 2*q];
                            float v1 = __uint_as_float(rh[2*q+1]) + bias[nc + 2*q+1];
                            __half2 h2 = __floats2half2_rn(tanh_fast(v0), tanh_fast(v1));
                            packed[q] = *reinterpret_cast<uint32_t*>(&h2);
                        }
                        uint4* dst = reinterpret_cast<uint4*>(g_h + (size_t)m * nout + nc);
                        #pragma unroll
                        for (int q = 0; q < 4; q++) dst[q] = reinterpret_cast<uint4*>(packed)[q];
                    } else {
                        float vals[32];
                        #pragma unroll
                        for (int q = 0; q < 32; q++)
                            vals[q] = __uint_as_float(rh[q]) + bias[nc + q];
                        const size_t off = (size_t)m * nout + nc;
                        uint32_t packed[16];
                        if (!last) {
                            float4* da = reinterpret_cast<float4*>(g_acc + off);
                            const float4* dx = reinterpret_cast<const float4*>(xc + off);
                            #pragma unroll
                            for (int q = 0; q < 8; q++) {
                                float4 v = reinterpret_cast<float4*>(vals)[q];
                                float4 a;
                                if (first) { a = v; }
                                else {
                                    a = da[q];
                                    a.x += wcoef * v.x; a.y += wcoef * v.y;
                                    a.z += wcoef * v.z; a.w += wcoef * v.w;
                                }
                                da[q] = a;
                                float4 xo = dx[q];
                                __half2 h0 = __floats2half2_rn(fmaf(ccn, v.x, xo.x), fmaf(ccn, v.y, xo.y));
                                __half2 h1 = __floats2half2_rn(fmaf(ccn, v.z, xo.z), fmaf(ccn, v.w, xo.w));
                                packed[2*q]   = *reinterpret_cast<uint32_t*>(&h0);
                                packed[2*q+1] = *reinterpret_cast<uint32_t*>(&h1);
                            }
                        } else {
                            const float4* da = reinterpret_cast<const float4*>(g_acc + off);
                            float4* dx = reinterpret_cast<float4*>(xc + off);
                            #pragma unroll
                            for (int q = 0; q < 8; q++) {
                                float4 v = reinterpret_cast<float4*>(vals)[q];
                                float4 a = da[q];
                                float4 xo = dx[q];
                                float4 xn;
                                xn.x = fmaf(s6, a.x + v.x, xo.x);
                                xn.y = fmaf(s6, a.y + v.y, xo.y);
                                xn.z = fmaf(s6, a.z + v.z, xo.z);
                                xn.w = fmaf(s6, a.w + v.w, xo.w);
                                dx[q] = xn;
                                __half2 h0 = __floats2half2_rn(xn.x, xn.y);
                                __half2 h1 = __floats2half2_rn(xn.z, xn.w);
                                packed[2*q]   = *reinterpret_cast<uint32_t*>(&h0);
                                packed[2*q+1] = *reinterpret_cast<uint32_t*>(&h1);
                            }
                        }
                        uint4* de = reinterpret_cast<uint4*>(g_xe + off);
                        #pragma unroll
                        for (int q = 0; q < 4; q++) de[q] = reinterpret_cast<uint4*>(packed)[q];
                    }
                }
                TC_FENCE_BEFORE();
                asm volatile("bar.sync 1, 128;" ::: "memory");
                if (wid == 0 && lane == 0) mbar_arrive_leader(mb_accfree + 8*b);
            }
        }

        grid_barrier(phase);
    }

    if (wid == 0) { TC_RELINQ_CG2(); TC_DEALLOC_CG2(tmem, 512); }
    cluster_sync();

#else  // ---------------- fallback: fp32 FFMA phase loop (plain sm_103) ----
    extern __shared__ char smem[];
    float* As = reinterpret_cast<float*>(smem);
    float* Bs = reinterpret_cast<float*>(smem + 8192);

    const int tid = threadIdx.x;
    const int pairId = (int)(blockIdx.x >> 1);
    const int rk = (int)(blockIdx.x & 1);
    const int tx = tid & 15, ty = tid >> 4;
    const int lr = tid >> 1;
    const int lc = (tid & 1) * 8;

    for (int phase = 0; phase < NPH; phase++) {
        const int e  = (phase >> 1) & 3;
        const int g2 = phase & 1;
        const int K = g2 ? HH : DD;
        const int ntiles = g2 ? G2_NT : G1_NT;
        const __half* Araw = g2 ? g_h : g_xe;
        const float* Wraw = g2 ? W2raw : W1raw;
        const float* bias = g2 ? b2 : b1;
        const float wcoef = (e == 1 || e == 2) ? 2.0f : 1.0f;
        const float ccn   = (e == 0 || e == 1) ? 0.5f*dt : (e == 2 ? dt : 0.0f);
        const int first = (e == 0), last = (e == 3);
        const int nout = g2 ? DD : HH;

        for (int t = pairId; t < ntiles; t += NPAIRS) {
            const int mi = t & (MT - 1), ni = t >> 4;
            const int m0 = mi * BMP + rk * 128;
            for (int half = 0; half < 2; half++) {
                const int n0 = ni * BNP + half * 128;
                float acc[8][8];
                #pragma unroll
                for (int i = 0; i < 8; i++)
                    #pragma unroll
                    for (int jq = 0; jq < 8; jq++) acc[i][jq] = 0.0f;

                for (int k0 = 0; k0 < K; k0 += 16) {
                    {
                        uint4 v = *reinterpret_cast<const uint4*>(Araw + (size_t)(m0 + lr) * K + k0 + lc);
                        const __half* hp = reinterpret_cast<const __half*>(&v);
                        #pragma unroll
                        for (int jq = 0; jq < 8; jq++) As[(lc + jq) * 128 + lr] = __half2float(hp[jq]);
                    }
                    {
                        const float* src = Wraw + (size_t)(n0 + lr) * K + k0 + lc;
                        float4 v1 = reinterpret_cast<const float4*>(src)[0];
                        float4 v2 = reinterpret_cast<const float4*>(src)[1];
                        Bs[(lc + 0) * 128 + lr] = v1.x; Bs[(lc + 1) * 128 + lr] = v1.y;
                        Bs[(lc + 2) * 128 + lr] = v1.z; Bs[(lc + 3) * 128 + lr] = v1.w;
                        Bs[(lc + 4) * 128 + lr] = v2.x; Bs[(lc + 5) * 128 + lr] = v2.y;
                        Bs[(lc + 6) * 128 + lr] = v2.z; Bs[(lc + 7) * 128 + lr] = v2.w;
                    }
                    __syncthreads();
                    #pragma unroll
                    for (int kk = 0; kk < 16; kk++) {
                        float a[8], bb[8];
                        #pragma unroll
                        for (int i = 0; i < 8; i++) a[i] = As[kk * 128 + ty * 8 + i];
                        #pragma unroll
                        for (int jq = 0; jq < 8; jq++) bb[jq] = Bs[kk * 128 + tx * 8 + jq];
                        #pragma unroll
                        for (int i = 0; i < 8; i++)
                            #pragma unroll
                            for (int jq = 0; jq < 8; jq++) acc[i][jq] = fmaf(a[i], bb[jq], acc[i][jq]);
                    }
                    __syncthreads();
                }

                #pragma unroll
                for (int i = 0; i < 8; i++) {
                    int m = m0 + ty * 8 + i;
                    #pragma unroll
                    for (int jq = 0; jq < 8; jq++) {
                        int n = n0 + tx * 8 + jq;
                        float v = acc[i][jq] + bias[n];
                        size_t o = (size_t)m * nout + n;
                        if (!g2) {
                            g_h[o] = __float2half_rn(tanh_fast(v));
                        } else if (!last) {
                            float a = first ? v : fmaf(wcoef, v, g_acc[o]);
                            g_acc[o] = a;
                            g_xe[o] = __float2half_rn(fmaf(ccn, v, xc[o]));
                        } else {
                            float xn = fmaf(s6, g_acc[o] + v, xc[o]);
                            xc[o] = xn;
                            g_xe[o] = __float2half_rn(xn);
                        }
                    }
                }
                __syncthreads();
            }
        }
        grid_barrier(phase);
    }
#endif
}

// --------------------------- setup kernels --------------------------------
__global__ void wconv_kernel(const float* __restrict__ W, __half* __restrict__ Wh, int n)
{
    int i = blockIdx.x * blockDim.x + threadIdx.x;
    if (i < n) Wh[i] = __float2half_rn(W[i]);
}

__global__ void prep_kernel(const float* __restrict__ xcin, __half* __restrict__ xe, int n)
{
    int i = blockIdx.x * blockDim.x + threadIdx.x;
    if (i < n) xe[i] = __float2half_rn(xcin[i]);
}

__global__ void zero_bar_kernel()
{
    int i = blockIdx.x * blockDim.x + threadIdx.x;
    if (i < NPH) g_bar[i] = 0u;
}

// ------------------------------- host side --------------------------------
typedef CUresult (*EncodeTiledFn)(
    CUtensorMap*, CUtensorMapDataType, cuuint32_t, void*,
    const cuuint64_t*, const cuuint64_t*, const cuuint32_t*, const cuuint32_t*,
    CUtensorMapInterleave, CUtensorMapSwizzle, CUtensorMapL2promotion, CUtensorMapFloatOOBfill);

static void encode_2d_f16(EncodeTiledFn fn, CUtensorMap* m, void* ptr,
                          uint64_t d0, uint64_t d1)
{
    if (!fn) return;
    cuuint64_t dims[2]    = {d0, d1};
    cuuint64_t strides[1] = {d0 * 2};
    cuuint32_t box[2]     = {BK, 128};
    cuuint32_t es[2]      = {1, 1};
    fn(m, CU_TENSOR_MAP_DATA_TYPE_FLOAT16, 2, ptr, dims, strides, box, es,
       CU_TENSOR_MAP_INTERLEAVE_NONE, CU_TENSOR_MAP_SWIZZLE_128B,
       CU_TENSOR_MAP_L2_PROMOTION_L2_128B, CU_TENSOR_MAP_FLOAT_OOB_FILL_NONE);
}

extern "C" void kernel_launch(void* const* d_in, const int* in_sizes, int n_in,
                              void* d_out, int out_size)
{
    const float* x  = (const float*)d_in[0];
    const float* W1 = (const float*)d_in[1];
    const float* b1 = (const float*)d_in[2];
    const float* W2 = (const float*)d_in[3];
    const float* b2 = (const float*)d_in[4];
    float* xc = (float*)d_out;

    void *pW1h, *pW2h, *pxe, *ph;
    cudaGetSymbolAddress(&pW1h, g_W1h);
    cudaGetSymbolAddress(&pW2h, g_W2h);
    cudaGetSymbolAddress(&pxe,  g_xe);
    cudaGetSymbolAddress(&ph,   g_h);

    EncodeTiledFn encode_fn = nullptr;
    cudaDriverEntryPointQueryResult qres;
    cudaGetDriverEntryPoint("cuTensorMapEncodeTiled", (void**)&encode_fn,
                            cudaEnableDefault, &qres);

    cudaFuncSetAttribute(ode_mega_kernel, cudaFuncAttributeMaxDynamicSharedMemorySize, SMEM_REQ);

    alignas(64) CUtensorMap tmA1, tmB1, tmA2, tmB2;
    memset(&tmA1, 0, sizeof(tmA1)); memset(&tmB1, 0, sizeof(tmB1));
    memset(&tmA2, 0, sizeof(tmA2)); memset(&tmB2, 0, sizeof(tmB2));
    encode_2d_f16(encode_fn, &tmA1, pxe,  DD, BB);   // xe  [4096 x 1024]
    encode_2d_f16(encode_fn, &tmB1, pW1h, DD, HH);   // W1h [4096 x 1024]
    encode_2d_f16(encode_fn, &tmA2, ph,   HH, BB);   // h   [4096 x 4096]
    encode_2d_f16(encode_fn, &tmB2, pW2h, HH, DD);   // W2h [1024 x 4096]

    const int nelem = BB * DD;
    const int EB = 256;

    cudaMemcpyAsync(xc, x, (size_t)nelem * sizeof(float), cudaMemcpyDeviceToDevice);
    prep_kernel<<<(nelem + EB - 1)/EB, EB>>>(xc, (__half*)pxe, nelem);
    wconv_kernel<<<(HH*DD + EB - 1)/EB, EB>>>(W1, (__half*)pW1h, HH*DD);
    wconv_kernel<<<(DD*HH + EB - 1)/EB, EB>>>(W2, (__half*)pW2h, DD*HH);
    zero_bar_kernel<<<(NPH + EB - 1)/EB, EB>>>();

    ode_mega_kernel<<<GRIDC, 256, SMEM_REQ>>>(
        tmA1, tmB1, tmA2, tmB2, b1, b2, xc, W1, W2);

    (void)in_sizes; (void)n_in; (void)out_size;
}